// round 15
// baseline (speedup 1.0000x reference)
#include <cuda_runtime.h>
#include <cstdint>
#include <cstddef>

#define NB 4
#define NN 4096
#define CC 128
#define KF 384
#define SEG (NN*CC)        /* 524288 floats per [N,C] slab */
#define SBATCH (3*SEG)     /* per-batch Z0|Z1|Z2 flat buffer */

/* ---- cheb GEMM: BM=128, warps 2(M)x2(N)x2(Ksplit), warp tile 64x64 ---- */
#define BM 128
#define BK 32
#define ASTR 36
#define BSTR 136
#define NSTAGE 4
#define STAGE_F (BM*ASTR + BK*BSTR)   /* 8960 floats per stage */
#define SMEM_BYTES (NSTAGE*STAGE_F*4) /* 143360 B */

/* ---- out GEMM config: BM=64, 2 CTAs/SM ---- */
#define OBM 64
#define OSTAGE 4
#define OSTAGE_F (OBM*ASTR + BK*BSTR)
#define OSMEM (OSTAGE*OSTAGE_F*4)

extern __shared__ char smem_raw[];

__device__ __align__(256) float g_zcat[NB*SBATCH];   // 25.2 MB flat Z buffer
__device__ __align__(256) float g_deg [NB*NN];
__device__ __align__(256) float g_degp[16*NB*NN];
__device__ __align__(256) float g_wt  [KF*CC];       // pre-rounded tf32
__device__ __align__(256) float g_xr  [NB*SEG];      // x pre-rounded tf32
__device__ __align__(256) float g_z1r [NB*SEG];      // Z1 pre-rounded tf32

__device__ __forceinline__ uint32_t f2tf32(float x){
    uint32_t r; asm("cvt.rna.tf32.f32 %0, %1;" : "=r"(r) : "f"(x)); return r;
}
__device__ __forceinline__ void cp16(void* dst, const void* src){
    uint32_t d = (uint32_t)__cvta_generic_to_shared(dst);
    asm volatile("cp.async.cg.shared.global [%0], [%1], 16;" :: "r"(d), "l"(src));
}
#define MMA_TF32(ac, a0,a1,a2,a3, b0,b1) \
    asm volatile( \
        "mma.sync.aligned.m16n8k8.row.col.f32.tf32.tf32.f32 " \
        "{%0,%1,%2,%3}, {%4,%5,%6,%7}, {%8,%9}, {%0,%1,%2,%3};" \
        : "+f"((ac)[0]), "+f"((ac)[1]), "+f"((ac)[2]), "+f"((ac)[3]) \
        : "r"(a0), "r"(a1), "r"(a2), "r"(a3), "r"(b0), "r"(b1))

/* W' [f][o] = rna(W[o][f]) */
__global__ void wt_kernel(const float* __restrict__ W){
    int i = blockIdx.x*256 + threadIdx.x;
    if(i < KF*CC){ int f = i/CC, o = i%CC;
        g_wt[i] = __uint_as_float(f2tf32(W[o*KF + f])); }
}

/* g_xr = rna(x) (B operand of cheb<0>), and copy exact x into zcat seg0 */
__global__ void xr_kernel(const float* __restrict__ x){
    int i = blockIdx.x*256 + threadIdx.x;
    float4 v = *(const float4*)(x + (size_t)i*4);
    int b = (i*4)/SEG, off = (i*4)%SEG;
    *(float4*)(g_zcat + (size_t)b*SBATCH + off) = v;
    float4 r;
    r.x = __uint_as_float(f2tf32(v.x));
    r.y = __uint_as_float(f2tf32(v.y));
    r.z = __uint_as_float(f2tf32(v.z));
    r.w = __uint_as_float(f2tf32(v.w));
    *(float4*)(g_xr + (size_t)i*4) = r;
}

/* degree[b,j] = sum_i adj[b,i,j]; deterministic two-stage reduction */
__global__ void degree_partial(const float* __restrict__ adj){
    int b  = blockIdx.y;
    int j  = blockIdx.x*1024 + threadIdx.x*4;
    int i0 = blockIdx.z*256;
    const float* p = adj + (size_t)b*NN*NN + (size_t)i0*NN + j;
    float4 s = make_float4(0.f,0.f,0.f,0.f);
    #pragma unroll 4
    for(int i=0;i<256;i++){
        float4 v = *(const float4*)(p + (size_t)i*NN);
        s.x+=v.x; s.y+=v.y; s.z+=v.z; s.w+=v.w;
    }
    *(float4*)(g_degp + (size_t)blockIdx.z*NB*NN + (size_t)b*NN + j) = s;
}
__global__ void degree_reduce(){
    int i = blockIdx.x*256 + threadIdx.x;
    float s = 0.f;
    #pragma unroll
    for(int z=0;z<16;z++) s += g_degp[(size_t)z*NB*NN + i];
    g_deg[i] = s;
}

/* MODE 0: Z1 = lr*(D*x - A@x) - x            (B = g_xr,  writes Z1 + rounded Z1)
   MODE 1: Z2 = 2*(lr*(D*Z1 - A@Z1) - Z1) - x (B = g_z1r, writes Z2)
   Warp layout: wk = warp&1 (K half), wn = (warp>>1)&1, wm = warp>>2.
   Warp tile 64x64, k-slice 16 per warp; partials reduced through smem. */
template<int MODE>
__global__ void __launch_bounds__(256, 1) cheb_gemm(
        const float* __restrict__ adj, const float* __restrict__ x)
{
    constexpr int KT = NN / BK;
    const int b  = blockIdx.y;
    const int n0 = blockIdx.x * BM;

    const float* Atile = adj + (size_t)b*NN*NN + (size_t)n0*NN;
    const float* Bb    = ((MODE==0) ? g_xr : g_z1r) + (size_t)b*SEG;

    float* smem = (float*)smem_raw;
    const int tid  = threadIdx.x;
    const int warp = tid >> 5, lane = tid & 31;
    const int wk = warp & 1, wn = (warp >> 1) & 1, wm = warp >> 2;
    const int g  = lane >> 2, tg = lane & 3;

    float acc[4][8][4];
    #pragma unroll
    for(int i=0;i<4;i++)
        #pragma unroll
        for(int j=0;j<8;j++)
            #pragma unroll
            for(int k=0;k<4;k++) acc[i][j][k]=0.f;

    /* hoisted per-thread constants */
    const int a_soff = (tid>>3)*ASTR + (tid&7)*4;          /* cp.async A smem   */
    const size_t a_goff = (size_t)(tid>>3)*NN + (tid&7)*4; /* cp.async A global */
    const int b_soff = (tid>>5)*BSTR + (tid&31)*4;
    const size_t b_goff = (size_t)(tid>>5)*CC + (tid&31)*4;
    const int frA = (wm*64 + g)*ASTR + tg + wk*16;          /* frag A base off  */
    const int frB = BM*ASTR + (tg + wk*16)*BSTR + wn*64 + g;/* frag B base off  */

    auto load_tiles = [&](int kt){
        float* As = smem + (kt & (NSTAGE-1))*STAGE_F;
        float* Bs = As + BM*ASTR;
        const float* Asrc = Atile + kt*BK;
        const float* Bsrc = Bb + (size_t)(kt*BK)*CC;
        #pragma unroll
        for(int l=0;l<4;l++)   /* A: 128x32 = 1024 float4 */
            cp16(As + l*32*ASTR + a_soff, Asrc + (size_t)l*32*NN + a_goff);
        #pragma unroll
        for(int l=0;l<4;l++)   /* B: 32x128 = 1024 float4 */
            cp16(Bs + l*8*BSTR + b_soff, Bsrc + (size_t)l*8*CC + b_goff);
        asm volatile("cp.async.commit_group;");
    };

    load_tiles(0); load_tiles(1); load_tiles(2);

    #pragma unroll 1
    for(int kt=0; kt<KT; kt++){
        if(kt+3 < KT){
            load_tiles(kt+3);
            asm volatile("cp.async.wait_group 3;");
        } else if(kt+2 < KT){
            asm volatile("cp.async.wait_group 2;");
        } else if(kt+1 < KT){
            asm volatile("cp.async.wait_group 1;");
        } else {
            asm volatile("cp.async.wait_group 0;");
        }
        __syncthreads();

        const float* Ab0 = smem + (kt & (NSTAGE-1))*STAGE_F + frA;
        const float* Bb0 = smem + (kt & (NSTAGE-1))*STAGE_F + frB;

        #pragma unroll
        for(int s=0; s<2; s++){          /* this warp's two k8 slices */
            uint32_t afr[4][4];
            #pragma unroll
            for(int mi=0; mi<4; mi++){
                afr[mi][0] = __float_as_uint(Ab0[mi*16*ASTR +           s*8    ]);
                afr[mi][1] = __float_as_uint(Ab0[mi*16*ASTR + 8*ASTR +  s*8    ]);
                afr[mi][2] = __float_as_uint(Ab0[mi*16*ASTR +           s*8 + 4]);
                afr[mi][3] = __float_as_uint(Ab0[mi*16*ASTR + 8*ASTR +  s*8 + 4]);
            }
            uint32_t bfr[8][2];
            #pragma unroll
            for(int ni=0; ni<8; ni++){
                bfr[ni][0] = __float_as_uint(Bb0[ s*8   *BSTR + ni*8]);
                bfr[ni][1] = __float_as_uint(Bb0[(s*8+4)*BSTR + ni*8]);
            }
            #pragma unroll
            for(int mi=0; mi<4; mi++)
                #pragma unroll
                for(int ni=0; ni<8; ni++)
                    MMA_TF32(acc[mi][ni],
                             afr[mi][0], afr[mi][1], afr[mi][2], afr[mi][3],
                             bfr[ni][0], bfr[ni][1]);
        }
        __syncthreads();
    }

    /* K-split reduction: wk=1 stores partials, wk=0 adds them. */
    {
        float* red = smem + (wm*2 + wn)*4096;   /* 16 KB per warp pair */
        if (wk == 1){
            #pragma unroll
            for(int mi=0; mi<4; mi++)
                #pragma unroll
                for(int ni=0; ni<8; ni++)
                    *(float4*)(red + (mi*8+ni)*128 + lane*4) =
                        make_float4(acc[mi][ni][0], acc[mi][ni][1],
                                    acc[mi][ni][2], acc[mi][ni][3]);
        }
        __syncthreads();
        if (wk == 0){
            #pragma unroll
            for(int mi=0; mi<4; mi++)
                #pragma unroll
                for(int ni=0; ni<8; ni++){
                    float4 v = *(const float4*)(red + (mi*8+ni)*128 + lane*4);
                    acc[mi][ni][0] += v.x; acc[mi][ni][1] += v.y;
                    acc[mi][ni][2] += v.z; acc[mi][ni][3] += v.w;
                }
        }
    }

    if (wk != 0) return;

    const float LR = 2.0f / (2.0f + 1e-6f);
    const float* zin = (MODE==0) ? (x + (size_t)b*SEG)
                                 : (g_zcat + (size_t)b*SBATCH + SEG);
    const float* x0  = x + (size_t)b*SEG;
    float* zout = g_zcat + (size_t)b*SBATCH + (MODE==0 ? SEG : 2*SEG);
    float* z1r  = g_z1r + (size_t)b*SEG;

    #pragma unroll
    for(int mi=0; mi<4; mi++)
        #pragma unroll
        for(int half=0; half<2; half++){
            const int r = n0 + wm*64 + mi*16 + g + half*8;
            const float dg = g_deg[b*NN + r];
            #pragma unroll
            for(int ni=0; ni<8; ni++){
                const int c = wn*64 + ni*8 + 2*tg;
                float v0 = acc[mi][ni][half*2];
                float v1 = acc[mi][ni][half*2+1];
                float2 z = *(const float2*)(zin + (size_t)r*CC + c);
                if(MODE == 0){
                    float o0 = LR*(dg*z.x - v0) - z.x;
                    float o1 = LR*(dg*z.y - v1) - z.y;
                    *(float2*)(zout + (size_t)r*CC + c) = make_float2(o0, o1);
                    *(float2*)(z1r  + (size_t)r*CC + c) =
                        make_float2(__uint_as_float(f2tf32(o0)),
                                    __uint_as_float(f2tf32(o1)));
                } else {
                    float2 xv = *(const float2*)(x0 + (size_t)r*CC + c);
                    float o0 = 2.f*(LR*(dg*z.x - v0) - z.x) - xv.x;
                    float o1 = 2.f*(LR*(dg*z.y - v1) - z.y) - xv.y;
                    *(float2*)(zout + (size_t)r*CC + c) = make_float2(o0, o1);
                }
            }
        }
}

/* out = Zflat[4096x384] @ W'^T  (A = exact zcat, cvt'ed; B = pre-rounded g_wt) */
__global__ void __launch_bounds__(256, 2) out_gemm(float* __restrict__ out)
{
    constexpr int KT = KF / BK;   /* 12 */
    const int b  = blockIdx.y;
    const int n0 = blockIdx.x * OBM;

    const float* Atile = g_zcat + (size_t)b*SBATCH + (size_t)n0 * KF;
    const float* Bb = (const float*)g_wt;

    float* smem = (float*)smem_raw;
    const int tid  = threadIdx.x;
    const int warp = tid >> 5, lane = tid & 31;
    const int wm = warp & 1, wn = warp >> 1;   /* 2 x 4, warp tile 32x32 */
    const int g  = lane >> 2, tg = lane & 3;

    float acc[2][4][4];
    #pragma unroll
    for(int i=0;i<2;i++)
        #pragma unroll
        for(int j=0;j<4;j++)
            #pragma unroll
            for(int k=0;k<4;k++) acc[i][j][k]=0.f;

    const int a_soff = (tid>>3)*ASTR + (tid&7)*4;
    const size_t a_goff = (size_t)(tid>>3)*KF + (tid&7)*4;
    const int b_soff = (tid>>5)*BSTR + (tid&31)*4;
    const size_t b_goff = (size_t)(tid>>5)*CC + (tid&31)*4;

    auto load_tiles = [&](int kt){
        float* As = smem + (kt & (OSTAGE-1))*OSTAGE_F;
        float* Bs = As + OBM*ASTR;
        const float* Asrc = Atile + kt*BK;
        const float* Bsrc = Bb + (size_t)(kt*BK)*CC;
        #pragma unroll
        for(int l=0;l<2;l++)
            cp16(As + l*32*ASTR + a_soff, Asrc + (size_t)l*32*KF + a_goff);
        #pragma unroll
        for(int l=0;l<4;l++)
            cp16(Bs + l*8*BSTR + b_soff, Bsrc + (size_t)l*8*CC + b_goff);
        asm volatile("cp.async.commit_group;");
    };

    load_tiles(0); load_tiles(1); load_tiles(2);

    #pragma unroll 1
    for(int kt=0; kt<KT; kt++){
        if(kt+3 < KT){
            load_tiles(kt+3);
            asm volatile("cp.async.wait_group 3;");
        } else if(kt+2 < KT){
            asm volatile("cp.async.wait_group 2;");
        } else if(kt+1 < KT){
            asm volatile("cp.async.wait_group 1;");
        } else {
            asm volatile("cp.async.wait_group 0;");
        }
        __syncthreads();

        const float* As = smem + (kt & (OSTAGE-1))*OSTAGE_F;
        const float* Bs = As + OBM*ASTR;

        #pragma unroll
        for(int ks=0; ks<4; ks++){
            const int kk = ks*8;
            uint32_t afr[2][4];
            #pragma unroll
            for(int mi=0; mi<2; mi++){
                const int ra = wm*32 + mi*16;
                afr[mi][0] = f2tf32(As[(ra+g  )*ASTR + kk+tg  ]);
                afr[mi][1] = f2tf32(As[(ra+g+8)*ASTR + kk+tg  ]);
                afr[mi][2] = f2tf32(As[(ra+g  )*ASTR + kk+tg+4]);
                afr[mi][3] = f2tf32(As[(ra+g+8)*ASTR + kk+tg+4]);
            }
            uint32_t bfr[4][2];
            #pragma unroll
            for(int ni=0; ni<4; ni++){
                const int cb = wn*32 + ni*8 + g;
                bfr[ni][0] = __float_as_uint(Bs[(kk+tg  )*BSTR + cb]);
                bfr[ni][1] = __float_as_uint(Bs[(kk+tg+4)*BSTR + cb]);
            }
            #pragma unroll
            for(int mi=0; mi<2; mi++)
                #pragma unroll
                for(int ni=0; ni<4; ni++)
                    MMA_TF32(acc[mi][ni],
                             afr[mi][0], afr[mi][1], afr[mi][2], afr[mi][3],
                             bfr[ni][0], bfr[ni][1]);
        }
        __syncthreads();
    }

    float* ob = out + (size_t)b*SEG;
    #pragma unroll
    for(int mi=0; mi<2; mi++)
        #pragma unroll
        for(int half=0; half<2; half++){
            const int r = n0 + wm*32 + mi*16 + g + half*8;
            #pragma unroll
            for(int ni=0; ni<4; ni++){
                const int c = wn*32 + ni*8 + 2*tg;
                *(float2*)(ob + (size_t)r*CC + c) =
                    make_float2(acc[mi][ni][half*2], acc[mi][ni][half*2+1]);
            }
        }
}

extern "C" void kernel_launch(void* const* d_in, const int* in_sizes, int n_in,
                              void* d_out, int out_size){
    const float* x   = (const float*)d_in[0];
    const float* adj = (const float*)d_in[1];
    const float* W   = (const float*)d_in[2];
    float* out = (float*)d_out;
    (void)in_sizes; (void)n_in; (void)out_size;

    cudaFuncSetAttribute(cheb_gemm<0>, cudaFuncAttributeMaxDynamicSharedMemorySize, SMEM_BYTES);
    cudaFuncSetAttribute(cheb_gemm<1>, cudaFuncAttributeMaxDynamicSharedMemorySize, SMEM_BYTES);
    cudaFuncSetAttribute(out_gemm,    cudaFuncAttributeMaxDynamicSharedMemorySize, OSMEM);

    wt_kernel<<<(KF*CC + 255)/256, 256>>>(W);
    xr_kernel<<<(NB*SEG/4 + 255)/256, 256>>>(x);
    degree_partial<<<dim3(NN/1024, NB, 16), 256>>>(adj);
    degree_reduce<<<(NB*NN)/256, 256>>>();

    dim3 grid(NN/BM, NB);   /* 32 x 4 = 128 CTAs */
    cheb_gemm<0><<<grid, 256, SMEM_BYTES>>>(adj, x);
    cheb_gemm<1><<<grid, 256, SMEM_BYTES>>>(adj, x);

    out_gemm<<<dim3(NN/OBM, NB), 256, OSMEM>>>(out);
}

// round 16
// speedup vs baseline: 1.4693x; 1.4693x over previous
#include <cuda_runtime.h>
#include <cstdint>
#include <cstddef>

#define NB 4
#define NN 4096
#define CC 128
#define KF 384
#define SEG (NN*CC)        /* 524288 floats per [N,C] slab */
#define SBATCH (3*SEG)     /* per-batch Z0|Z1|Z2 flat buffer */

/* ---- cheb GEMM config: BM=128, 4x2 warp grid, warp tile 32x64 ---- */
#define BM 128
#define BK 32
#define ASTR 36            /* A smem row stride: conflict-free for frag loads */
#define BSTR 136           /* B smem row stride: conflict-free for frag loads */
#define NSTAGE 4
#define STAGE_F (BM*ASTR + BK*BSTR)   /* 8960 floats per stage */
#define SMEM_BYTES (NSTAGE*STAGE_F*4) /* 143360 B */

/* ---- out GEMM config: BM=64, 2 CTAs/SM ---- */
#define OBM 64
#define OSTAGE 4
#define OSTAGE_F (OBM*ASTR + BK*BSTR) /* 6656 floats */
#define OSMEM (OSTAGE*OSTAGE_F*4)     /* 106496 B */

extern __shared__ char smem_raw[];

__device__ __align__(256) float g_zcat[NB*SBATCH];   // 25.2 MB flat Z buffer
__device__ __align__(256) float g_deg [NB*NN];
__device__ __align__(256) float g_degp[16*NB*NN];
__device__ __align__(256) float g_wt  [KF*CC];       // pre-rounded tf32
__device__ __align__(256) float g_xr  [NB*SEG];      // x pre-rounded tf32
__device__ __align__(256) float g_z1r [NB*SEG];      // Z1 pre-rounded tf32

__device__ __forceinline__ uint32_t f2tf32(float x){
    uint32_t r; asm("cvt.rna.tf32.f32 %0, %1;" : "=r"(r) : "f"(x)); return r;
}
__device__ __forceinline__ void cp16(void* dst, const void* src){
    uint32_t d = (uint32_t)__cvta_generic_to_shared(dst);
    asm volatile("cp.async.cg.shared.global [%0], [%1], 16;" :: "r"(d), "l"(src));
}
#define MMA_TF32(ac, a0,a1,a2,a3, b0,b1) \
    asm volatile( \
        "mma.sync.aligned.m16n8k8.row.col.f32.tf32.tf32.f32 " \
        "{%0,%1,%2,%3}, {%4,%5,%6,%7}, {%8,%9}, {%0,%1,%2,%3};" \
        : "+f"((ac)[0]), "+f"((ac)[1]), "+f"((ac)[2]), "+f"((ac)[3]) \
        : "r"(a0), "r"(a1), "r"(a2), "r"(a3), "r"(b0), "r"(b1))

/* W' [f][o] = rna(W[o][f]) — pre-rounded so out_gemm B needs no cvt */
__global__ void wt_kernel(const float* __restrict__ W){
    int i = blockIdx.x*256 + threadIdx.x;
    if(i < KF*CC){ int f = i/CC, o = i%CC;
        g_wt[i] = __uint_as_float(f2tf32(W[o*KF + f])); }
}

/* g_xr = rna(x) (B operand of cheb<0>), and copy exact x into zcat seg0 */
__global__ void xr_kernel(const float* __restrict__ x){
    int i = blockIdx.x*256 + threadIdx.x;
    float4 v = *(const float4*)(x + (size_t)i*4);
    int b = (i*4)/SEG, off = (i*4)%SEG;
    *(float4*)(g_zcat + (size_t)b*SBATCH + off) = v;
    float4 r;
    r.x = __uint_as_float(f2tf32(v.x));
    r.y = __uint_as_float(f2tf32(v.y));
    r.z = __uint_as_float(f2tf32(v.z));
    r.w = __uint_as_float(f2tf32(v.w));
    *(float4*)(g_xr + (size_t)i*4) = r;
}

/* degree[b,j] = sum_i adj[b,i,j]; deterministic two-stage reduction */
__global__ void degree_partial(const float* __restrict__ adj){
    int b  = blockIdx.y;
    int j  = blockIdx.x*1024 + threadIdx.x*4;
    int i0 = blockIdx.z*256;
    const float* p = adj + (size_t)b*NN*NN + (size_t)i0*NN + j;
    float4 s = make_float4(0.f,0.f,0.f,0.f);
    #pragma unroll 4
    for(int i=0;i<256;i++){
        float4 v = *(const float4*)(p + (size_t)i*NN);
        s.x+=v.x; s.y+=v.y; s.z+=v.z; s.w+=v.w;
    }
    *(float4*)(g_degp + (size_t)blockIdx.z*NB*NN + (size_t)b*NN + j) = s;
}
__global__ void degree_reduce(){
    int i = blockIdx.x*256 + threadIdx.x;
    float s = 0.f;
    #pragma unroll
    for(int z=0;z<16;z++) s += g_degp[(size_t)z*NB*NN + i];
    g_deg[i] = s;
}

/* MODE 0: Z1 = lr*(D*x - A@x) - x            (B = g_xr,  writes Z1 + rounded Z1)
   MODE 1: Z2 = 2*(lr*(D*Z1 - A@Z1) - Z1) - x (B = g_z1r, writes Z2)
   Inner loop: no cvt (A HW-truncated, B pre-rounded), fragment addresses
   hoisted to two base pointers per k-tile — all LDS use immediate offsets. */
template<int MODE>
__global__ void __launch_bounds__(256, 1) cheb_gemm(
        const float* __restrict__ adj, const float* __restrict__ x)
{
    constexpr int KT = NN / BK;
    const int b  = blockIdx.y;
    const int n0 = blockIdx.x * BM;

    const float* Atile = adj + (size_t)b*NN*NN + (size_t)n0*NN;
    const float* Bb    = ((MODE==0) ? g_xr : g_z1r) + (size_t)b*SEG;

    float* smem = (float*)smem_raw;
    const int tid  = threadIdx.x;
    const int warp = tid >> 5, lane = tid & 31;
    const int wm = warp & 3, wn = warp >> 2;   // 4 x 2 warp grid, tile 32x64
    const int g  = lane >> 2, tg = lane & 3;

    float acc[2][8][4];
    #pragma unroll
    for(int i=0;i<2;i++)
        #pragma unroll
        for(int j=0;j<8;j++)
            #pragma unroll
            for(int k=0;k<4;k++) acc[i][j][k]=0.f;

    /* hoisted per-thread constants */
    const int a_soff = (tid>>3)*ASTR + (tid&7)*4;
    const size_t a_goff = (size_t)(tid>>3)*NN + (tid&7)*4;
    const int b_soff = (tid>>5)*BSTR + (tid&31)*4;
    const size_t b_goff = (size_t)(tid>>5)*CC + (tid&31)*4;
    const int frA = (wm*32 + g)*ASTR + tg;              /* frag A base offset */
    const int frB = BM*ASTR + tg*BSTR + wn*64 + g;      /* frag B base offset */

    auto load_tiles = [&](int kt){
        float* As = smem + (kt & (NSTAGE-1))*STAGE_F;
        float* Bs = As + BM*ASTR;
        const float* Asrc = Atile + kt*BK;
        const float* Bsrc = Bb + (size_t)(kt*BK)*CC;
        #pragma unroll
        for(int l=0;l<4;l++)   /* A: 128x32 = 1024 float4 */
            cp16(As + l*32*ASTR + a_soff, Asrc + (size_t)l*32*NN + a_goff);
        #pragma unroll
        for(int l=0;l<4;l++)   /* B: 32x128 = 1024 float4 */
            cp16(Bs + l*8*BSTR + b_soff, Bsrc + (size_t)l*8*CC + b_goff);
        asm volatile("cp.async.commit_group;");
    };

    load_tiles(0); load_tiles(1); load_tiles(2);

    #pragma unroll 1
    for(int kt=0; kt<KT; kt++){
        if(kt+3 < KT){
            load_tiles(kt+3);
            asm volatile("cp.async.wait_group 3;");
        } else if(kt+2 < KT){
            asm volatile("cp.async.wait_group 2;");
        } else if(kt+1 < KT){
            asm volatile("cp.async.wait_group 1;");
        } else {
            asm volatile("cp.async.wait_group 0;");
        }
        __syncthreads();

        const float* Ab0 = smem + (kt & (NSTAGE-1))*STAGE_F + frA;
        const float* Bb0 = smem + (kt & (NSTAGE-1))*STAGE_F + frB;

        #pragma unroll
        for(int ks=0; ks<4; ks++){
            uint32_t afr[2][4];
            #pragma unroll
            for(int mi=0; mi<2; mi++){
                afr[mi][0] = __float_as_uint(Ab0[mi*16*ASTR +          ks*8    ]);
                afr[mi][1] = __float_as_uint(Ab0[mi*16*ASTR + 8*ASTR + ks*8    ]);
                afr[mi][2] = __float_as_uint(Ab0[mi*16*ASTR +          ks*8 + 4]);
                afr[mi][3] = __float_as_uint(Ab0[mi*16*ASTR + 8*ASTR + ks*8 + 4]);
            }
            uint32_t bfr[8][2];
            #pragma unroll
            for(int ni=0; ni<8; ni++){
                bfr[ni][0] = __float_as_uint(Bb0[ ks*8   *BSTR + ni*8]);
                bfr[ni][1] = __float_as_uint(Bb0[(ks*8+4)*BSTR + ni*8]);
            }
            #pragma unroll
            for(int mi=0; mi<2; mi++)
                #pragma unroll
                for(int ni=0; ni<8; ni++)
                    MMA_TF32(acc[mi][ni],
                             afr[mi][0], afr[mi][1], afr[mi][2], afr[mi][3],
                             bfr[ni][0], bfr[ni][1]);
        }
        __syncthreads();
    }

    const float LR = 2.0f / (2.0f + 1e-6f);
    const float* zin = (MODE==0) ? (x + (size_t)b*SEG)
                                 : (g_zcat + (size_t)b*SBATCH + SEG);
    const float* x0  = x + (size_t)b*SEG;
    float* zout = g_zcat + (size_t)b*SBATCH + (MODE==0 ? SEG : 2*SEG);
    float* z1r  = g_z1r + (size_t)b*SEG;

    #pragma unroll
    for(int mi=0; mi<2; mi++)
        #pragma unroll
        for(int half=0; half<2; half++){
            const int r = n0 + wm*32 + mi*16 + g + half*8;
            const float dg = g_deg[b*NN + r];
            #pragma unroll
            for(int ni=0; ni<8; ni++){
                const int c = wn*64 + ni*8 + 2*tg;
                float v0 = acc[mi][ni][half*2];
                float v1 = acc[mi][ni][half*2+1];
                float2 z = *(const float2*)(zin + (size_t)r*CC + c);
                if(MODE == 0){
                    float o0 = LR*(dg*z.x - v0) - z.x;
                    float o1 = LR*(dg*z.y - v1) - z.y;
                    *(float2*)(zout + (size_t)r*CC + c) = make_float2(o0, o1);
                    *(float2*)(z1r  + (size_t)r*CC + c) =
                        make_float2(__uint_as_float(f2tf32(o0)),
                                    __uint_as_float(f2tf32(o1)));
                } else {
                    float2 xv = *(const float2*)(x0 + (size_t)r*CC + c);
                    float o0 = 2.f*(LR*(dg*z.x - v0) - z.x) - xv.x;
                    float o1 = 2.f*(LR*(dg*z.y - v1) - z.y) - xv.y;
                    *(float2*)(zout + (size_t)r*CC + c) = make_float2(o0, o1);
                }
            }
        }
}

/* out = Zflat[4096x384] @ W'^T  (A = exact zcat, cvt'ed; B = pre-rounded g_wt) */
__global__ void __launch_bounds__(256, 2) out_gemm(float* __restrict__ out)
{
    constexpr int KT = KF / BK;   /* 12 */
    const int b  = blockIdx.y;
    const int n0 = blockIdx.x * OBM;

    const float* Atile = g_zcat + (size_t)b*SBATCH + (size_t)n0 * KF;
    const float* Bb = (const float*)g_wt;

    float* smem = (float*)smem_raw;
    const int tid  = threadIdx.x;
    const int warp = tid >> 5, lane = tid & 31;
    const int wm = warp & 1, wn = warp >> 1;   /* 2 x 4, warp tile 32x32 */
    const int g  = lane >> 2, tg = lane & 3;

    float acc[2][4][4];
    #pragma unroll
    for(int i=0;i<2;i++)
        #pragma unroll
        for(int j=0;j<4;j++)
            #pragma unroll
            for(int k=0;k<4;k++) acc[i][j][k]=0.f;

    const int a_soff = (tid>>3)*ASTR + (tid&7)*4;
    const size_t a_goff = (size_t)(tid>>3)*KF + (tid&7)*4;
    const int b_soff = (tid>>5)*BSTR + (tid&31)*4;
    const size_t b_goff = (size_t)(tid>>5)*CC + (tid&31)*4;
    const int frA = (wm*32 + g)*ASTR + tg;
    const int frB = OBM*ASTR + tg*BSTR + wn*32 + g;

    auto load_tiles = [&](int kt){
        float* As = smem + (kt & (OSTAGE-1))*OSTAGE_F;
        float* Bs = As + OBM*ASTR;
        const float* Asrc = Atile + kt*BK;
        const float* Bsrc = Bb + (size_t)(kt*BK)*CC;
        #pragma unroll
        for(int l=0;l<2;l++)
            cp16(As + l*32*ASTR + a_soff, Asrc + (size_t)l*32*KF + a_goff);
        #pragma unroll
        for(int l=0;l<4;l++)
            cp16(Bs + l*8*BSTR + b_soff, Bsrc + (size_t)l*8*CC + b_goff);
        asm volatile("cp.async.commit_group;");
    };

    load_tiles(0); load_tiles(1); load_tiles(2);

    #pragma unroll 1
    for(int kt=0; kt<KT; kt++){
        if(kt+3 < KT){
            load_tiles(kt+3);
            asm volatile("cp.async.wait_group 3;");
        } else if(kt+2 < KT){
            asm volatile("cp.async.wait_group 2;");
        } else if(kt+1 < KT){
            asm volatile("cp.async.wait_group 1;");
        } else {
            asm volatile("cp.async.wait_group 0;");
        }
        __syncthreads();

        const float* Ab0 = smem + (kt & (OSTAGE-1))*OSTAGE_F + frA;
        const float* Bb0 = smem + (kt & (OSTAGE-1))*OSTAGE_F + frB;

        #pragma unroll
        for(int ks=0; ks<4; ks++){
            uint32_t afr[2][4];
            #pragma unroll
            for(int mi=0; mi<2; mi++){
                afr[mi][0] = f2tf32(Ab0[mi*16*ASTR +          ks*8    ]);
                afr[mi][1] = f2tf32(Ab0[mi*16*ASTR + 8*ASTR + ks*8    ]);
                afr[mi][2] = f2tf32(Ab0[mi*16*ASTR +          ks*8 + 4]);
                afr[mi][3] = f2tf32(Ab0[mi*16*ASTR + 8*ASTR + ks*8 + 4]);
            }
            uint32_t bfr[4][2];
            #pragma unroll
            for(int ni=0; ni<4; ni++){
                bfr[ni][0] = __float_as_uint(Bb0[ ks*8   *BSTR + ni*8]);
                bfr[ni][1] = __float_as_uint(Bb0[(ks*8+4)*BSTR + ni*8]);
            }
            #pragma unroll
            for(int mi=0; mi<2; mi++)
                #pragma unroll
                for(int ni=0; ni<4; ni++)
                    MMA_TF32(acc[mi][ni],
                             afr[mi][0], afr[mi][1], afr[mi][2], afr[mi][3],
                             bfr[ni][0], bfr[ni][1]);
        }
        __syncthreads();
    }

    float* ob = out + (size_t)b*SEG;
    #pragma unroll
    for(int mi=0; mi<2; mi++)
        #pragma unroll
        for(int half=0; half<2; half++){
            const int r = n0 + wm*32 + mi*16 + g + half*8;
            #pragma unroll
            for(int ni=0; ni<4; ni++){
                const int c = wn*32 + ni*8 + 2*tg;
                *(float2*)(ob + (size_t)r*CC + c) =
                    make_float2(acc[mi][ni][half*2], acc[mi][ni][half*2+1]);
            }
        }
}

extern "C" void kernel_launch(void* const* d_in, const int* in_sizes, int n_in,
                              void* d_out, int out_size){
    const float* x   = (const float*)d_in[0];
    const float* adj = (const float*)d_in[1];
    const float* W   = (const float*)d_in[2];
    float* out = (float*)d_out;
    (void)in_sizes; (void)n_in; (void)out_size;

    cudaFuncSetAttribute(cheb_gemm<0>, cudaFuncAttributeMaxDynamicSharedMemorySize, SMEM_BYTES);
    cudaFuncSetAttribute(cheb_gemm<1>, cudaFuncAttributeMaxDynamicSharedMemorySize, SMEM_BYTES);
    cudaFuncSetAttribute(out_gemm,    cudaFuncAttributeMaxDynamicSharedMemorySize, OSMEM);

    wt_kernel<<<(KF*CC + 255)/256, 256>>>(W);
    xr_kernel<<<(NB*SEG/4 + 255)/256, 256>>>(x);
    degree_partial<<<dim3(NN/1024, NB, 16), 256>>>(adj);
    degree_reduce<<<(NB*NN)/256, 256>>>();

    dim3 grid(NN/BM, NB);   /* 32 x 4 = 128 CTAs */
    cheb_gemm<0><<<grid, 256, SMEM_BYTES>>>(adj, x);
    cheb_gemm<1><<<grid, 256, SMEM_BYTES>>>(adj, x);

    out_gemm<<<dim3(NN/OBM, NB), 256, OSMEM>>>(out);
}